// round 14
// baseline (speedup 1.0000x reference)
#include <cuda_runtime.h>
#include <cuda_bf16.h>
#include <math.h>

#define NN 4096
#define EE 131072
#define DIN 72
#define DD 256
#define HH 8
#define HDD 32
#define DEMB 128
#define TT 5

// ---------------- scratch (device globals; no runtime allocation) ----------------
__device__ float g_h  [NN * DD];
__device__ float g_pre[NN * DD];
__device__ float g_t  [NN * 768];
__device__ float g_t2 [NN * DD];
__device__ float g_ao [NN * DD];
__device__ float g_emb[NN * DEMB];

// ---------------- tf32 mma helpers ----------------
__device__ __forceinline__ unsigned cvt_tf32(float x) {
    unsigned r;
    asm("cvt.rna.tf32.f32 %0, %1;" : "=r"(r) : "f"(x));
    return r;
}
__device__ __forceinline__ void mma_tf32(float* c, const unsigned* a,
                                         unsigned b0, unsigned b1) {
    asm volatile(
        "mma.sync.aligned.m16n8k8.row.col.f32.tf32.tf32.f32 "
        "{%0,%1,%2,%3}, {%4,%5,%6,%7}, {%8,%9}, {%0,%1,%2,%3};\n"
        : "+f"(c[0]), "+f"(c[1]), "+f"(c[2]), "+f"(c[3])
        : "r"(a[0]), "r"(a[1]), "r"(a[2]), "r"(a[3]), "r"(b0), "r"(b1));
}

// ---------------- activations ----------------
__device__ __forceinline__ float act_elu(float v) {
    return v > 0.f ? v : expm1f(v);
}
__device__ __forceinline__ float act_gelu_tanh(float v) {
    const float c = 0.7978845608028654f;   // sqrt(2/pi)
    float u = c * (v + 0.044715f * v * v * v);
    return 0.5f * v * (1.f + tanhf(u));
}

// ---------------- tf32 MMA GEMM: C = act(A @ W^T + b) ----------------
// Block: 256 threads = 8 warps (2m x 4n), tile 32x64, BK=64 (zero-filled tail).
// Dynamic smem: As[2][32][68] | Bs[2][64][68] = 52224 B (pitch 68 => 4*gr+gq banks).
// WPRE: additionally write pre[m*256+n] = (1+eps[0])*C_val  (requires Nout==256).
template <int ACT, bool WPRE>
__global__ __launch_bounds__(256)
void gemm_mma_kernel(const float* __restrict__ A, const float* __restrict__ W,
                     const float* __restrict__ bias, float* __restrict__ C,
                     int M, int Nout, int K,
                     float* __restrict__ pre, const float* __restrict__ eps)
{
    extern __shared__ __align__(16) unsigned gsm[];
    unsigned (*As)[32][68] = (unsigned(*)[32][68])gsm;                 // 2 bufs
    unsigned (*Bs)[64][68] = (unsigned(*)[64][68])(gsm + 2 * 32 * 68); // 2 bufs

    const int tid = threadIdx.x;
    const int lane = tid & 31;
    const int wid = tid >> 5;
    const int gr = lane >> 2;
    const int gq = lane & 3;
    const int wm = (wid >> 2) * 16;
    const int wn = (wid & 3) * 16;
    const int m0 = blockIdx.y * 32, n0 = blockIdx.x * 64;

    float acc[2][4];
    #pragma unroll
    for (int ni = 0; ni < 2; ni++)
        #pragma unroll
        for (int f = 0; f < 4; f++) acc[ni][f] = 0.f;

    const int KT = (K + 63) >> 6;

    uint4 pa[2], pb[4];

    auto fetch = [&](int kt) {
        #pragma unroll
        for (int u = 0; u < 2; u++) {   // A: 32 rows x 16 col-groups = 512 uint4
            int i = tid + u * 256;
            int r = i >> 4, cg = i & 15;
            int k = kt * 64 + cg * 4;
            uint4 va = {0u, 0u, 0u, 0u};
            if (k < K) {
                float4 fa = *(const float4*)&A[(size_t)(m0 + r) * K + k];
                va.x = cvt_tf32(fa.x); va.y = cvt_tf32(fa.y);
                va.z = cvt_tf32(fa.z); va.w = cvt_tf32(fa.w);
            }
            pa[u] = va;
        }
        #pragma unroll
        for (int u = 0; u < 4; u++) {   // B: 64 rows x 16 col-groups = 1024 uint4
            int i = tid + u * 256;
            int r = i >> 4, cg = i & 15;
            int k = kt * 64 + cg * 4;
            uint4 vb = {0u, 0u, 0u, 0u};
            if (k < K) {
                float4 fb = *(const float4*)&W[(size_t)(n0 + r) * K + k];
                vb.x = cvt_tf32(fb.x); vb.y = cvt_tf32(fb.y);
                vb.z = cvt_tf32(fb.z); vb.w = cvt_tf32(fb.w);
            }
            pb[u] = vb;
        }
    };
    auto stash = [&](int buf) {
        #pragma unroll
        for (int u = 0; u < 2; u++) {
            int i = tid + u * 256;
            int r = i >> 4, cg = i & 15;
            *(uint4*)&As[buf][r][cg * 4] = pa[u];
        }
        #pragma unroll
        for (int u = 0; u < 4; u++) {
            int i = tid + u * 256;
            int r = i >> 4, cg = i & 15;
            *(uint4*)&Bs[buf][r][cg * 4] = pb[u];
        }
    };

    fetch(0);
    stash(0);
    __syncthreads();

    for (int kt = 0; kt < KT; kt++) {
        const int cur = kt & 1;
        if (kt + 1 < KT) fetch(kt + 1);

        const unsigned (*Ac)[68] = As[cur];
        const unsigned (*Bc)[68] = Bs[cur];
        #pragma unroll
        for (int kk = 0; kk < 8; kk++) {
            unsigned a[4];
            const int rr = wm + gr;
            a[0] = Ac[rr][kk * 8 + gq];
            a[1] = Ac[rr + 8][kk * 8 + gq];
            a[2] = Ac[rr][kk * 8 + gq + 4];
            a[3] = Ac[rr + 8][kk * 8 + gq + 4];
            #pragma unroll
            for (int ni = 0; ni < 2; ni++) {
                unsigned b0 = Bc[wn + ni * 8 + gr][kk * 8 + gq];
                unsigned b1 = Bc[wn + ni * 8 + gr][kk * 8 + gq + 4];
                mma_tf32(acc[ni], a, b0, b1);
            }
        }

        if (kt + 1 < KT) stash(cur ^ 1);
        __syncthreads();
    }

    float s = 1.f;
    if (WPRE) s = 1.f + eps[0];

    const int m = m0 + wm + gr;
    #pragma unroll
    for (int ni = 0; ni < 2; ni++) {
        const int n = n0 + wn + ni * 8 + 2 * gq;
        float b0 = bias[n], b1 = bias[n + 1];
        float2 w0, w1;
        w0.x = acc[ni][0] + b0; w0.y = acc[ni][1] + b1;
        w1.x = acc[ni][2] + b0; w1.y = acc[ni][3] + b1;
        if (ACT == 1) {
            w0.x = act_elu(w0.x); w0.y = act_elu(w0.y);
            w1.x = act_elu(w1.x); w1.y = act_elu(w1.y);
        }
        if (ACT == 2) {
            w0.x = act_gelu_tanh(w0.x); w0.y = act_gelu_tanh(w0.y);
            w1.x = act_gelu_tanh(w1.x); w1.y = act_gelu_tanh(w1.y);
        }
        *(float2*)&C[(size_t)m * Nout + n] = w0;
        *(float2*)&C[(size_t)(m + 8) * Nout + n] = w1;
        if (WPRE) {
            float2 p0, p1;
            p0.x = s * w0.x; p0.y = s * w0.y;
            p1.x = s * w1.x; p1.y = s * w1.y;
            *(float2*)&pre[(size_t)m * 256 + n] = p0;
            *(float2*)&pre[(size_t)(m + 8) * 256 + n] = p1;
        }
    }
}

#define GEMM_SMEM ((2 * 32 * 68 + 2 * 64 * 68) * 4)

// ---------------- dedicated head-2 kernel: out[4096,5] = emb @ w2^T + b2 ----------------
__global__ __launch_bounds__(256)
void head2_kernel(const float* __restrict__ emb, const float* __restrict__ w,
                  const float* __restrict__ b, float* __restrict__ out)
{
    int idx = blockIdx.x * 256 + threadIdx.x;   // 128 blocks x 256 = 32768 >= 4096*8
    int row = idx >> 3, col = idx & 7;
    if (col >= TT) return;
    const float4* er = (const float4*)&emb[(size_t)row * DEMB];
    const float4* wr = (const float4*)&w[(size_t)col * DEMB];
    float s = 0.f;
    #pragma unroll
    for (int k = 0; k < DEMB / 4; k++) {
        float4 a = er[k];
        float4 c = wr[k];
        s += a.x * c.x + a.y * c.y + a.z * c.z + a.w * c.w;
    }
    out[(size_t)row * TT + col] = s + b[col];
}

// ---------------- GIN edge aggregation: 8 floats/thread, red.global.add.v4 ----------------
__global__ __launch_bounds__(256)
void gin_agg_kernel(const int* __restrict__ ei,
                    const float* __restrict__ x, float* __restrict__ pre)
{
    long long gid = (long long)blockIdx.x * blockDim.x + threadIdx.x;
    int e = (int)(gid >> 5);
    int c = ((int)gid & 31) * 8;
    if (e >= EE) return;
    int src = ei[e];
    int dst = ei[EE + e];
    float4 v0 = *(const float4*)&x[src * DD + c];
    float4 v1 = *(const float4*)&x[src * DD + c + 4];
    float* a0 = &pre[dst * DD + c];
    float* a1 = a0 + 4;
    asm volatile("red.global.add.v4.f32 [%0], {%1, %2, %3, %4};"
                 :: "l"(a0), "f"(v0.x), "f"(v0.y), "f"(v0.z), "f"(v0.w) : "memory");
    asm volatile("red.global.add.v4.f32 [%0], {%1, %2, %3, %4};"
                 :: "l"(a1), "f"(v1.x), "f"(v1.y), "f"(v1.z), "f"(v1.w) : "memory");
}

// ---------------- fused LayerNorm (+opt ELU) + residual, one-pass ----------------
template <int ACT, bool WPRE>
__global__ __launch_bounds__(256)
void ln_res_kernel(const float* __restrict__ in, const float* __restrict__ g,
                   const float* __restrict__ b, float* __restrict__ x,
                   float* __restrict__ pre, const float* __restrict__ eps)
{
    __shared__ float w1[8], w2[8];
    const int row = blockIdx.x, tid = threadIdx.x;
    const int lane = tid & 31, wid = tid >> 5;
    float v = in[row * DD + tid];

    float s1 = v, s2 = v * v;
    #pragma unroll
    for (int off = 16; off > 0; off >>= 1) {
        s1 += __shfl_xor_sync(0xffffffffu, s1, off);
        s2 += __shfl_xor_sync(0xffffffffu, s2, off);
    }
    if (lane == 0) { w1[wid] = s1; w2[wid] = s2; }
    __syncthreads();
    float t1 = 0.f, t2 = 0.f;
    #pragma unroll
    for (int i = 0; i < 8; i++) { t1 += w1[i]; t2 += w2[i]; }

    float mu = t1 * (1.f / DD);
    float var = t2 * (1.f / DD) - mu * mu;

    float y = (v - mu) * rsqrtf(var + 1e-5f) * g[tid] + b[tid];
    if (ACT == 1) y = act_elu(y);
    float xn = x[row * DD + tid] + y;
    x[row * DD + tid] = xn;
    if (WPRE) pre[row * DD + tid] = (1.f + eps[0]) * xn;
}

// ---------------- flash attention via tf32 mma.sync, BM=128, KV tile 128 ----------------
__global__ __launch_bounds__(256)
void flash_mma_kernel(const float* __restrict__ qkv, float* __restrict__ out)
{
    extern __shared__ __align__(16) unsigned fsm[];
    unsigned (*Ks)[36]  = (unsigned(*)[36])fsm;
    unsigned (*Vs)[36]  = (unsigned(*)[36])(fsm + 128 * 36);
    unsigned (*Ps)[132] = (unsigned(*)[132])(fsm + 2 * 128 * 36);

    const int tid = threadIdx.x;
    const int lane = tid & 31;
    const int wid = tid >> 5;
    const int hh = blockIdx.y;
    const int q0 = blockIdx.x * 128;
    const int gr = lane >> 2;
    const int gq = lane & 3;
    const float scale = 0.17677669529663689f;  // 1/sqrt(32)

    const int r0 = wid * 16 + gr;
    const int r1 = r0 + 8;

    unsigned aq[4][4];
    {
        const float* p0 = &qkv[(q0 + r0) * 768 + hh * 32];
        const float* p1 = &qkv[(q0 + r1) * 768 + hh * 32];
        #pragma unroll
        for (int kk = 0; kk < 4; kk++) {
            aq[kk][0] = cvt_tf32(p0[kk * 8 + gq] * scale);
            aq[kk][1] = cvt_tf32(p1[kk * 8 + gq] * scale);
            aq[kk][2] = cvt_tf32(p0[kk * 8 + gq + 4] * scale);
            aq[kk][3] = cvt_tf32(p1[kk * 8 + gq + 4] * scale);
        }
    }

    float m0 = -1e30f, l0 = 0.f, m1 = -1e30f, l1 = 0.f;
    float o[4][4];
    #pragma unroll
    for (int n = 0; n < 4; n++)
        #pragma unroll
        for (int f = 0; f < 4; f++) o[n][f] = 0.f;

    for (int t0 = 0; t0 < NN; t0 += 128) {
        __syncthreads();
        #pragma unroll
        for (int i = tid; i < 1024; i += 256) {
            int r = i >> 3, d = (i & 7) * 4;
            float4 kv = *(const float4*)&qkv[(t0 + r) * 768 + 256 + hh * 32 + d];
            float4 vv = *(const float4*)&qkv[(t0 + r) * 768 + 512 + hh * 32 + d];
            uint4 kt, vt;
            kt.x = cvt_tf32(kv.x); kt.y = cvt_tf32(kv.y);
            kt.z = cvt_tf32(kv.z); kt.w = cvt_tf32(kv.w);
            vt.x = cvt_tf32(vv.x); vt.y = cvt_tf32(vv.y);
            vt.z = cvt_tf32(vv.z); vt.w = cvt_tf32(vv.w);
            *(uint4*)&Ks[r][d] = kt;
            *(uint4*)&Vs[r][d] = vt;
        }
        __syncthreads();

        float sc[16][4];
        #pragma unroll
        for (int nn = 0; nn < 16; nn++) {
            sc[nn][0] = 0.f; sc[nn][1] = 0.f; sc[nn][2] = 0.f; sc[nn][3] = 0.f;
            #pragma unroll
            for (int kk = 0; kk < 4; kk++) {
                unsigned b0 = Ks[nn * 8 + gr][kk * 8 + gq];
                unsigned b1 = Ks[nn * 8 + gr][kk * 8 + gq + 4];
                mma_tf32(sc[nn], aq[kk], b0, b1);
            }
        }

        float rmax0 = -1e30f, rmax1 = -1e30f;
        #pragma unroll
        for (int nn = 0; nn < 16; nn++) {
            rmax0 = fmaxf(rmax0, fmaxf(sc[nn][0], sc[nn][1]));
            rmax1 = fmaxf(rmax1, fmaxf(sc[nn][2], sc[nn][3]));
        }
        rmax0 = fmaxf(rmax0, __shfl_xor_sync(0xffffffffu, rmax0, 1));
        rmax0 = fmaxf(rmax0, __shfl_xor_sync(0xffffffffu, rmax0, 2));
        rmax1 = fmaxf(rmax1, __shfl_xor_sync(0xffffffffu, rmax1, 1));
        rmax1 = fmaxf(rmax1, __shfl_xor_sync(0xffffffffu, rmax1, 2));

        float nm0 = fmaxf(m0, rmax0), alpha0 = __expf(m0 - nm0);
        float nm1 = fmaxf(m1, rmax1), alpha1 = __expf(m1 - nm1);

        float ps0 = 0.f, ps1 = 0.f;
        #pragma unroll
        for (int nn = 0; nn < 16; nn++) {
            float p00 = __expf(sc[nn][0] - nm0);
            float p01 = __expf(sc[nn][1] - nm0);
            float p10 = __expf(sc[nn][2] - nm1);
            float p11 = __expf(sc[nn][3] - nm1);
            ps0 += p00 + p01;
            ps1 += p10 + p11;
            uint2 w0, w1;
            w0.x = cvt_tf32(p00); w0.y = cvt_tf32(p01);
            w1.x = cvt_tf32(p10); w1.y = cvt_tf32(p11);
            *(uint2*)&Ps[r0][nn * 8 + 2 * gq] = w0;
            *(uint2*)&Ps[r1][nn * 8 + 2 * gq] = w1;
        }
        ps0 += __shfl_xor_sync(0xffffffffu, ps0, 1);
        ps0 += __shfl_xor_sync(0xffffffffu, ps0, 2);
        ps1 += __shfl_xor_sync(0xffffffffu, ps1, 1);
        ps1 += __shfl_xor_sync(0xffffffffu, ps1, 2);

        l0 = l0 * alpha0 + ps0; m0 = nm0;
        l1 = l1 * alpha1 + ps1; m1 = nm1;

        #pragma unroll
        for (int nn = 0; nn < 4; nn++) {
            o[nn][0] *= alpha0; o[nn][1] *= alpha0;
            o[nn][2] *= alpha1; o[nn][3] *= alpha1;
        }

        __syncwarp();

        #pragma unroll
        for (int kk = 0; kk < 16; kk++) {
            unsigned pa[4];
            pa[0] = Ps[r0][kk * 8 + gq];
            pa[1] = Ps[r1][kk * 8 + gq];
            pa[2] = Ps[r0][kk * 8 + gq + 4];
            pa[3] = Ps[r1][kk * 8 + gq + 4];
            #pragma unroll
            for (int nn = 0; nn < 4; nn++) {
                unsigned b0 = Vs[kk * 8 + gq][nn * 8 + gr];
                unsigned b1 = Vs[kk * 8 + gq + 4][nn * 8 + gr];
                mma_tf32(o[nn], pa, b0, b1);
            }
        }
        __syncwarp();
    }

    const float inv0 = 1.f / l0, inv1 = 1.f / l1;
    #pragma unroll
    for (int nn = 0; nn < 4; nn++) {
        float2 w0, w1;
        w0.x = o[nn][0] * inv0; w0.y = o[nn][1] * inv0;
        w1.x = o[nn][2] * inv1; w1.y = o[nn][3] * inv1;
        *(float2*)&out[(q0 + r0) * DD + hh * 32 + nn * 8 + 2 * gq] = w0;
        *(float2*)&out[(q0 + r1) * DD + hh * 32 + nn * 8 + 2 * gq] = w1;
    }
}

// ---------------- host orchestration ----------------
extern "C" void kernel_launch(void* const* d_in, const int* in_sizes, int n_in,
                              void* d_out, int out_size)
{
    const float*     x         = (const float*)d_in[0];
    const int*       ei        = (const int*)d_in[1];
    const float*     in_w      = (const float*)d_in[2];
    const float*     in_b      = (const float*)d_in[3];
    const float*     head_w1   = (const float*)d_in[4];
    const float*     head_b1   = (const float*)d_in[5];
    const float*     head_w2   = (const float*)d_in[6];
    const float*     head_b2   = (const float*)d_in[7];
    const float*     mlp_w1    = (const float*)d_in[8];
    const float*     mlp_b1    = (const float*)d_in[9];
    const float*     mlp_w2    = (const float*)d_in[10];
    const float*     mlp_b2    = (const float*)d_in[11];
    const float*     gin_eps   = (const float*)d_in[12];
    const float*     ln1_g     = (const float*)d_in[13];
    const float*     ln1_b     = (const float*)d_in[14];
    const float*     attn_in_w = (const float*)d_in[15];
    const float*     attn_in_b = (const float*)d_in[16];
    const float*     attn_out_w= (const float*)d_in[17];
    const float*     attn_out_b= (const float*)d_in[18];
    const float*     ln2_g     = (const float*)d_in[19];
    const float*     ln2_b     = (const float*)d_in[20];
    const float*     ffn_w1    = (const float*)d_in[21];
    const float*     ffn_b1    = (const float*)d_in[22];
    const float*     ffn_w2    = (const float*)d_in[23];
    const float*     ffn_b2    = (const float*)d_in[24];
    const float*     ln3_g     = (const float*)d_in[25];
    const float*     ln3_b     = (const float*)d_in[26];

    float *h, *pre, *t, *t2, *ao, *emb;
    cudaGetSymbolAddress((void**)&h,   g_h);
    cudaGetSymbolAddress((void**)&pre, g_pre);
    cudaGetSymbolAddress((void**)&t,   g_t);
    cudaGetSymbolAddress((void**)&t2,  g_t2);
    cudaGetSymbolAddress((void**)&ao,  g_ao);
    cudaGetSymbolAddress((void**)&emb, g_emb);

    const int FLASH_SMEM = (2 * 128 * 36 + 128 * 132) * 4;   // 104448 B
    cudaFuncSetAttribute(flash_mma_kernel,
                         cudaFuncAttributeMaxDynamicSharedMemorySize, FLASH_SMEM);
    cudaFuncSetAttribute(gemm_mma_kernel<0, false>,
                         cudaFuncAttributeMaxDynamicSharedMemorySize, GEMM_SMEM);
    cudaFuncSetAttribute(gemm_mma_kernel<1, false>,
                         cudaFuncAttributeMaxDynamicSharedMemorySize, GEMM_SMEM);
    cudaFuncSetAttribute(gemm_mma_kernel<2, false>,
                         cudaFuncAttributeMaxDynamicSharedMemorySize, GEMM_SMEM);
    cudaFuncSetAttribute(gemm_mma_kernel<1, true>,
                         cudaFuncAttributeMaxDynamicSharedMemorySize, GEMM_SMEM);

    // input proj + ELU; also writes pre = (1+eps[0]) * h  (GIN of layer 0)
    gemm_mma_kernel<1, true><<<dim3(DD / 64, NN / 32), 256, GEMM_SMEM>>>(
        x, in_w, in_b, h, NN, DD, DIN, pre, gin_eps);

    for (int l = 0; l < 2; l++) {
        // ---- GIN: pre already holds (1+eps_l)*h; add neighbor sums ----
        gin_agg_kernel<<<(EE * 32) / 256, 256>>>(ei, h, pre);
        gemm_mma_kernel<1, false><<<dim3(DD / 64, NN / 32), 256, GEMM_SMEM>>>(
            pre, mlp_w1 + (size_t)l * DD * DD, mlp_b1 + (size_t)l * DD, t, NN, DD, DD,
            nullptr, nullptr);
        gemm_mma_kernel<0, false><<<dim3(DD / 64, NN / 32), 256, GEMM_SMEM>>>(
            t, mlp_w2 + (size_t)l * DD * DD, mlp_b2 + (size_t)l * DD, t2, NN, DD, DD,
            nullptr, nullptr);
        ln_res_kernel<1, false><<<NN, 256>>>(
            t2, ln1_g + (size_t)l * DD, ln1_b + (size_t)l * DD, h, nullptr, nullptr);

        // ---- global attention ----
        gemm_mma_kernel<0, false><<<dim3(768 / 64, NN / 32), 256, GEMM_SMEM>>>(
            h, attn_in_w + (size_t)l * 768 * DD, attn_in_b + (size_t)l * 768, t, NN, 768, DD,
            nullptr, nullptr);
        flash_mma_kernel<<<dim3(NN / 128, HH), 256, FLASH_SMEM>>>(t, ao);
        gemm_mma_kernel<0, false><<<dim3(DD / 64, NN / 32), 256, GEMM_SMEM>>>(
            ao, attn_out_w + (size_t)l * DD * DD, attn_out_b + (size_t)l * DD, t2, NN, DD, DD,
            nullptr, nullptr);
        ln_res_kernel<0, false><<<NN, 256>>>(
            t2, ln2_g + (size_t)l * DD, ln2_b + (size_t)l * DD, h, nullptr, nullptr);

        // ---- FFN ----
        gemm_mma_kernel<2, false><<<dim3(512 / 64, NN / 32), 256, GEMM_SMEM>>>(
            h, ffn_w1 + (size_t)l * 512 * DD, ffn_b1 + (size_t)l * 512, t, NN, 512, DD,
            nullptr, nullptr);
        gemm_mma_kernel<0, false><<<dim3(DD / 64, NN / 32), 256, GEMM_SMEM>>>(
            t, ffn_w2 + (size_t)l * DD * 512, ffn_b2 + (size_t)l * DD, t2, NN, DD, 512,
            nullptr, nullptr);
        if (l == 0) {
            ln_res_kernel<0, true><<<NN, 256>>>(
                t2, ln3_g, ln3_b, h, pre, gin_eps + 1);
        } else {
            ln_res_kernel<0, false><<<NN, 256>>>(
                t2, ln3_g + (size_t)l * DD, ln3_b + (size_t)l * DD, h, nullptr, nullptr);
        }
    }

    // ---- head ----
    gemm_mma_kernel<1, false><<<dim3(DEMB / 64, NN / 32), 256, GEMM_SMEM>>>(
        h, head_w1, head_b1, emb, NN, DEMB, DD, nullptr, nullptr);
    head2_kernel<<<NN * 8 / 256, 256>>>(emb, head_w2, head_b2, (float*)d_out);
}

// round 15
// speedup vs baseline: 1.0301x; 1.0301x over previous
#include <cuda_runtime.h>
#include <cuda_bf16.h>
#include <math.h>

#define NN 4096
#define EE 131072
#define DIN 72
#define DD 256
#define HH 8
#define HDD 32
#define DEMB 128
#define TT 5

// ---------------- scratch (device globals; no runtime allocation) ----------------
__device__ float g_h  [NN * DD];
__device__ float g_pre[NN * DD];
__device__ float g_t  [NN * 768];
__device__ float g_t2 [NN * DD];
__device__ float g_ao [NN * DD];
__device__ float g_emb[NN * DEMB];

// ---------------- tf32 mma helpers ----------------
__device__ __forceinline__ unsigned cvt_tf32(float x) {
    unsigned r;
    asm("cvt.rna.tf32.f32 %0, %1;" : "=r"(r) : "f"(x));
    return r;
}
__device__ __forceinline__ void mma_tf32(float* c, const unsigned* a,
                                         unsigned b0, unsigned b1) {
    asm volatile(
        "mma.sync.aligned.m16n8k8.row.col.f32.tf32.tf32.f32 "
        "{%0,%1,%2,%3}, {%4,%5,%6,%7}, {%8,%9}, {%0,%1,%2,%3};\n"
        : "+f"(c[0]), "+f"(c[1]), "+f"(c[2]), "+f"(c[3])
        : "r"(a[0]), "r"(a[1]), "r"(a[2]), "r"(a[3]), "r"(b0), "r"(b1));
}

// ---------------- activations ----------------
__device__ __forceinline__ float act_elu(float v) {
    return v > 0.f ? v : expm1f(v);
}
__device__ __forceinline__ float act_gelu_tanh(float v) {
    const float c = 0.7978845608028654f;   // sqrt(2/pi)
    float u = c * (v + 0.044715f * v * v * v);
    return 0.5f * v * (1.f + tanhf(u));
}

// ---------------- tf32 MMA GEMM: C = act(A @ W^T + b) ----------------
// Block: 256 threads = 8 warps (2m x 4n), tile 32x64, BK=32 (zero-filled tail).
// WPRE: additionally write pre[m*256+n] = (1+eps[0])*C_val  (requires Nout==256).
template <int ACT, bool WPRE>
__global__ __launch_bounds__(256)
void gemm_mma_kernel(const float* __restrict__ A, const float* __restrict__ W,
                     const float* __restrict__ bias, float* __restrict__ C,
                     int M, int Nout, int K,
                     float* __restrict__ pre, const float* __restrict__ eps)
{
    __shared__ __align__(16) unsigned As[2][32][36];
    __shared__ __align__(16) unsigned Bs[2][64][36];

    const int tid = threadIdx.x;
    const int lane = tid & 31;
    const int wid = tid >> 5;
    const int gr = lane >> 2;
    const int gq = lane & 3;
    const int wm = (wid >> 2) * 16;
    const int wn = (wid & 3) * 16;
    const int m0 = blockIdx.y * 32, n0 = blockIdx.x * 64;

    float acc[2][4];
    #pragma unroll
    for (int ni = 0; ni < 2; ni++)
        #pragma unroll
        for (int f = 0; f < 4; f++) acc[ni][f] = 0.f;

    const int KT = (K + 31) >> 5;

    uint4 pa, pb[2];

    auto fetch = [&](int kt) {
        {
            int r = tid >> 3, cg = tid & 7;
            int k = kt * 32 + cg * 4;
            uint4 va = {0u, 0u, 0u, 0u};
            if (k < K) {
                float4 fa = *(const float4*)&A[(size_t)(m0 + r) * K + k];
                va.x = cvt_tf32(fa.x); va.y = cvt_tf32(fa.y);
                va.z = cvt_tf32(fa.z); va.w = cvt_tf32(fa.w);
            }
            pa = va;
        }
        #pragma unroll
        for (int u = 0; u < 2; u++) {
            int i = tid + u * 256;
            int r = i >> 3, cg = i & 7;
            int k = kt * 32 + cg * 4;
            uint4 vb = {0u, 0u, 0u, 0u};
            if (k < K) {
                float4 fb = *(const float4*)&W[(size_t)(n0 + r) * K + k];
                vb.x = cvt_tf32(fb.x); vb.y = cvt_tf32(fb.y);
                vb.z = cvt_tf32(fb.z); vb.w = cvt_tf32(fb.w);
            }
            pb[u] = vb;
        }
    };
    auto stash = [&](int buf) {
        {
            int r = tid >> 3, cg = tid & 7;
            *(uint4*)&As[buf][r][cg * 4] = pa;
        }
        #pragma unroll
        for (int u = 0; u < 2; u++) {
            int i = tid + u * 256;
            int r = i >> 3, cg = i & 7;
            *(uint4*)&Bs[buf][r][cg * 4] = pb[u];
        }
    };

    fetch(0);
    stash(0);
    __syncthreads();

    for (int kt = 0; kt < KT; kt++) {
        const int cur = kt & 1;
        if (kt + 1 < KT) fetch(kt + 1);

        const unsigned (*Ac)[36] = As[cur];
        const unsigned (*Bc)[36] = Bs[cur];
        #pragma unroll
        for (int kk = 0; kk < 4; kk++) {
            unsigned a[4];
            const int rr = wm + gr;
            a[0] = Ac[rr][kk * 8 + gq];
            a[1] = Ac[rr + 8][kk * 8 + gq];
            a[2] = Ac[rr][kk * 8 + gq + 4];
            a[3] = Ac[rr + 8][kk * 8 + gq + 4];
            #pragma unroll
            for (int ni = 0; ni < 2; ni++) {
                unsigned b0 = Bc[wn + ni * 8 + gr][kk * 8 + gq];
                unsigned b1 = Bc[wn + ni * 8 + gr][kk * 8 + gq + 4];
                mma_tf32(acc[ni], a, b0, b1);
            }
        }

        if (kt + 1 < KT) stash(cur ^ 1);
        __syncthreads();
    }

    float s = 1.f;
    if (WPRE) s = 1.f + eps[0];

    const int m = m0 + wm + gr;
    #pragma unroll
    for (int ni = 0; ni < 2; ni++) {
        const int n = n0 + wn + ni * 8 + 2 * gq;
        float b0 = bias[n], b1 = bias[n + 1];
        float2 w0, w1;
        w0.x = acc[ni][0] + b0; w0.y = acc[ni][1] + b1;
        w1.x = acc[ni][2] + b0; w1.y = acc[ni][3] + b1;
        if (ACT == 1) {
            w0.x = act_elu(w0.x); w0.y = act_elu(w0.y);
            w1.x = act_elu(w1.x); w1.y = act_elu(w1.y);
        }
        if (ACT == 2) {
            w0.x = act_gelu_tanh(w0.x); w0.y = act_gelu_tanh(w0.y);
            w1.x = act_gelu_tanh(w1.x); w1.y = act_gelu_tanh(w1.y);
        }
        *(float2*)&C[(size_t)m * Nout + n] = w0;
        *(float2*)&C[(size_t)(m + 8) * Nout + n] = w1;
        if (WPRE) {
            float2 p0, p1;
            p0.x = s * w0.x; p0.y = s * w0.y;
            p1.x = s * w1.x; p1.y = s * w1.y;
            *(float2*)&pre[(size_t)m * 256 + n] = p0;
            *(float2*)&pre[(size_t)(m + 8) * 256 + n] = p1;
        }
    }
}

// ---------------- dedicated head-2 kernel: out[4096,5] = emb @ w2^T + b2 ----------------
__global__ __launch_bounds__(256)
void head2_kernel(const float* __restrict__ emb, const float* __restrict__ w,
                  const float* __restrict__ b, float* __restrict__ out)
{
    int idx = blockIdx.x * 256 + threadIdx.x;   // 128 blocks x 256 = 32768 = 4096*8
    int row = idx >> 3, col = idx & 7;
    if (col >= TT) return;
    const float4* er = (const float4*)&emb[(size_t)row * DEMB];
    const float4* wr = (const float4*)&w[(size_t)col * DEMB];
    float s = 0.f;
    #pragma unroll
    for (int k = 0; k < DEMB / 4; k++) {
        float4 a = er[k];
        float4 c = wr[k];
        s += a.x * c.x + a.y * c.y + a.z * c.z + a.w * c.w;
    }
    out[(size_t)row * TT + col] = s + b[col];
}

// ---------------- GIN edge aggregation: vector red.global.add.v4.f32 ----------------
__global__ __launch_bounds__(256)
void gin_agg_kernel(const int* __restrict__ ei,
                    const float* __restrict__ x, float* __restrict__ pre)
{
    long long gid = (long long)blockIdx.x * blockDim.x + threadIdx.x;
    int e = (int)(gid >> 6);
    int c = ((int)gid & 63) * 4;
    if (e >= EE) return;
    int src = ei[e];
    int dst = ei[EE + e];
    float4 v = *(const float4*)&x[src * DD + c];
    float* a = &pre[dst * DD + c];
    asm volatile("red.global.add.v4.f32 [%0], {%1, %2, %3, %4};"
                 :: "l"(a), "f"(v.x), "f"(v.y), "f"(v.z), "f"(v.w)
                 : "memory");
}

// ---------------- fused LayerNorm (+opt ELU) + residual, one-pass ----------------
template <int ACT, bool WPRE>
__global__ __launch_bounds__(256)
void ln_res_kernel(const float* __restrict__ in, const float* __restrict__ g,
                   const float* __restrict__ b, float* __restrict__ x,
                   float* __restrict__ pre, const float* __restrict__ eps)
{
    __shared__ float w1[8], w2[8];
    const int row = blockIdx.x, tid = threadIdx.x;
    const int lane = tid & 31, wid = tid >> 5;
    float v = in[row * DD + tid];

    float s1 = v, s2 = v * v;
    #pragma unroll
    for (int off = 16; off > 0; off >>= 1) {
        s1 += __shfl_xor_sync(0xffffffffu, s1, off);
        s2 += __shfl_xor_sync(0xffffffffu, s2, off);
    }
    if (lane == 0) { w1[wid] = s1; w2[wid] = s2; }
    __syncthreads();
    float t1 = 0.f, t2 = 0.f;
    #pragma unroll
    for (int i = 0; i < 8; i++) { t1 += w1[i]; t2 += w2[i]; }

    float mu = t1 * (1.f / DD);
    float var = t2 * (1.f / DD) - mu * mu;

    float y = (v - mu) * rsqrtf(var + 1e-5f) * g[tid] + b[tid];
    if (ACT == 1) y = act_elu(y);
    float xn = x[row * DD + tid] + y;
    x[row * DD + tid] = xn;
    if (WPRE) pre[row * DD + tid] = (1.f + eps[0]) * xn;
}

// ---------------- flash attention via tf32 mma.sync, BM=128, KV tile 128 ----------------
// Block = 256 threads (8 warps), 128 q-rows; warp w owns rows w*16..w*16+15.
// grid = (N/128, H). Dynamic smem: Ks[128][36] | Vs[128][36] | Ps[128][132] (~102 KB).
__global__ __launch_bounds__(256)
void flash_mma_kernel(const float* __restrict__ qkv, float* __restrict__ out)
{
    extern __shared__ __align__(16) unsigned fsm[];
    unsigned (*Ks)[36]  = (unsigned(*)[36])fsm;
    unsigned (*Vs)[36]  = (unsigned(*)[36])(fsm + 128 * 36);
    unsigned (*Ps)[132] = (unsigned(*)[132])(fsm + 2 * 128 * 36);

    const int tid = threadIdx.x;
    const int lane = tid & 31;
    const int wid = tid >> 5;
    const int hh = blockIdx.y;
    const int q0 = blockIdx.x * 128;
    const int gr = lane >> 2;
    const int gq = lane & 3;
    const float scale = 0.17677669529663689f;  // 1/sqrt(32)

    const int r0 = wid * 16 + gr;   // 0..127
    const int r1 = r0 + 8;

    unsigned aq[4][4];
    {
        const float* p0 = &qkv[(q0 + r0) * 768 + hh * 32];
        const float* p1 = &qkv[(q0 + r1) * 768 + hh * 32];
        #pragma unroll
        for (int kk = 0; kk < 4; kk++) {
            aq[kk][0] = cvt_tf32(p0[kk * 8 + gq] * scale);
            aq[kk][1] = cvt_tf32(p1[kk * 8 + gq] * scale);
            aq[kk][2] = cvt_tf32(p0[kk * 8 + gq + 4] * scale);
            aq[kk][3] = cvt_tf32(p1[kk * 8 + gq + 4] * scale);
        }
    }

    float m0 = -1e30f, l0 = 0.f, m1 = -1e30f, l1 = 0.f;
    float o[4][4];
    #pragma unroll
    for (int n = 0; n < 4; n++)
        #pragma unroll
        for (int f = 0; f < 4; f++) o[n][f] = 0.f;

    for (int t0 = 0; t0 < NN; t0 += 128) {
        __syncthreads();
        #pragma unroll
        for (int i = tid; i < 1024; i += 256) {
            int r = i >> 3, d = (i & 7) * 4;
            float4 kv = *(const float4*)&qkv[(t0 + r) * 768 + 256 + hh * 32 + d];
            float4 vv = *(const float4*)&qkv[(t0 + r) * 768 + 512 + hh * 32 + d];
            uint4 kt, vt;
            kt.x = cvt_tf32(kv.x); kt.y = cvt_tf32(kv.y);
            kt.z = cvt_tf32(kv.z); kt.w = cvt_tf32(kv.w);
            vt.x = cvt_tf32(vv.x); vt.y = cvt_tf32(vv.y);
            vt.z = cvt_tf32(vv.z); vt.w = cvt_tf32(vv.w);
            *(uint4*)&Ks[r][d] = kt;
            *(uint4*)&Vs[r][d] = vt;
        }
        __syncthreads();

        // ---- S = Q K^T : 16 n-tiles (128 keys) x 4 k-steps ----
        float sc[16][4];
        #pragma unroll
        for (int nn = 0; nn < 16; nn++) {
            sc[nn][0] = 0.f; sc[nn][1] = 0.f; sc[nn][2] = 0.f; sc[nn][3] = 0.f;
            #pragma unroll
            for (int kk = 0; kk < 4; kk++) {
                unsigned b0 = Ks[nn * 8 + gr][kk * 8 + gq];
                unsigned b1 = Ks[nn * 8 + gr][kk * 8 + gq + 4];
                mma_tf32(sc[nn], aq[kk], b0, b1);
            }
        }

        float rmax0 = -1e30f, rmax1 = -1e30f;
        #pragma unroll
        for (int nn = 0; nn < 16; nn++) {
            rmax0 = fmaxf(rmax0, fmaxf(sc[nn][0], sc[nn][1]));
            rmax1 = fmaxf(rmax1, fmaxf(sc[nn][2], sc[nn][3]));
        }
        rmax0 = fmaxf(rmax0, __shfl_xor_sync(0xffffffffu, rmax0, 1));
        rmax0 = fmaxf(rmax0, __shfl_xor_sync(0xffffffffu, rmax0, 2));
        rmax1 = fmaxf(rmax1, __shfl_xor_sync(0xffffffffu, rmax1, 1));
        rmax1 = fmaxf(rmax1, __shfl_xor_sync(0xffffffffu, rmax1, 2));

        float nm0 = fmaxf(m0, rmax0), alpha0 = __expf(m0 - nm0);
        float nm1 = fmaxf(m1, rmax1), alpha1 = __expf(m1 - nm1);

        float ps0 = 0.f, ps1 = 0.f;
        #pragma unroll
        for (int nn = 0; nn < 16; nn++) {
            float p00 = __expf(sc[nn][0] - nm0);
            float p01 = __expf(sc[nn][1] - nm0);
            float p10 = __expf(sc[nn][2] - nm1);
            float p11 = __expf(sc[nn][3] - nm1);
            ps0 += p00 + p01;
            ps1 += p10 + p11;
            uint2 w0, w1;
            w0.x = cvt_tf32(p00); w0.y = cvt_tf32(p01);
            w1.x = cvt_tf32(p10); w1.y = cvt_tf32(p11);
            *(uint2*)&Ps[r0][nn * 8 + 2 * gq] = w0;
            *(uint2*)&Ps[r1][nn * 8 + 2 * gq] = w1;
        }
        ps0 += __shfl_xor_sync(0xffffffffu, ps0, 1);
        ps0 += __shfl_xor_sync(0xffffffffu, ps0, 2);
        ps1 += __shfl_xor_sync(0xffffffffu, ps1, 1);
        ps1 += __shfl_xor_sync(0xffffffffu, ps1, 2);

        l0 = l0 * alpha0 + ps0; m0 = nm0;
        l1 = l1 * alpha1 + ps1; m1 = nm1;

        #pragma unroll
        for (int nn = 0; nn < 4; nn++) {
            o[nn][0] *= alpha0; o[nn][1] *= alpha0;
            o[nn][2] *= alpha1; o[nn][3] *= alpha1;
        }

        __syncwarp();

        // ---- O += P V : 4 n-tiles (32 dims) x 16 k-steps (128 keys) ----
        #pragma unroll
        for (int kk = 0; kk < 16; kk++) {
            unsigned pa[4];
            pa[0] = Ps[r0][kk * 8 + gq];
            pa[1] = Ps[r1][kk * 8 + gq];
            pa[2] = Ps[r0][kk * 8 + gq + 4];
            pa[3] = Ps[r1][kk * 8 + gq + 4];
            #pragma unroll
            for (int nn = 0; nn < 4; nn++) {
                unsigned b0 = Vs[kk * 8 + gq][nn * 8 + gr];
                unsigned b1 = Vs[kk * 8 + gq + 4][nn * 8 + gr];
                mma_tf32(o[nn], pa, b0, b1);
            }
        }
        __syncwarp();
    }

    const float inv0 = 1.f / l0, inv1 = 1.f / l1;
    #pragma unroll
    for (int nn = 0; nn < 4; nn++) {
        float2 w0, w1;
        w0.x = o[nn][0] * inv0; w0.y = o[nn][1] * inv0;
        w1.x = o[nn][2] * inv1; w1.y = o[nn][3] * inv1;
        *(float2*)&out[(q0 + r0) * DD + hh * 32 + nn * 8 + 2 * gq] = w0;
        *(float2*)&out[(q0 + r1) * DD + hh * 32 + nn * 8 + 2 * gq] = w1;
    }
}

// ---------------- host orchestration ----------------
extern "C" void kernel_launch(void* const* d_in, const int* in_sizes, int n_in,
                              void* d_out, int out_size)
{
    const float*     x         = (const float*)d_in[0];
    const int*       ei        = (const int*)d_in[1];
    const float*     in_w      = (const float*)d_in[2];
    const float*     in_b      = (const float*)d_in[3];
    const float*     head_w1   = (const float*)d_in[4];
    const float*     head_b1   = (const float*)d_in[5];
    const float*     head_w2   = (const float*)d_in[6];
    const float*     head_b2   = (const float*)d_in[7];
    const float*     mlp_w1    = (const float*)d_in[8];
    const float*     mlp_b1    = (const float*)d_in[9];
    const float*     mlp_w2    = (const float*)d_in[10];
    const float*     mlp_b2    = (const float*)d_in[11];
    const float*     gin_eps   = (const float*)d_in[12];
    const float*     ln1_g     = (const float*)d_in[13];
    const float*     ln1_b     = (const float*)d_in[14];
    const float*     attn_in_w = (const float*)d_in[15];
    const float*     attn_in_b = (const float*)d_in[16];
    const float*     attn_out_w= (const float*)d_in[17];
    const float*     attn_out_b= (const float*)d_in[18];
    const float*     ln2_g     = (const float*)d_in[19];
    const float*     ln2_b     = (const float*)d_in[20];
    const float*     ffn_w1    = (const float*)d_in[21];
    const float*     ffn_b1    = (const float*)d_in[22];
    const float*     ffn_w2    = (const float*)d_in[23];
    const float*     ffn_b2    = (const float*)d_in[24];
    const float*     ln3_g     = (const float*)d_in[25];
    const float*     ln3_b     = (const float*)d_in[26];

    float *h, *pre, *t, *t2, *ao, *emb;
    cudaGetSymbolAddress((void**)&h,   g_h);
    cudaGetSymbolAddress((void**)&pre, g_pre);
    cudaGetSymbolAddress((void**)&t,   g_t);
    cudaGetSymbolAddress((void**)&t2,  g_t2);
    cudaGetSymbolAddress((void**)&ao,  g_ao);
    cudaGetSymbolAddress((void**)&emb, g_emb);

    const int FLASH_SMEM = (2 * 128 * 36 + 128 * 132) * 4;   // 104448 B
    cudaFuncSetAttribute(flash_mma_kernel,
                         cudaFuncAttributeMaxDynamicSharedMemorySize, FLASH_SMEM);

    // input proj + ELU; also writes pre = (1+eps[0]) * h  (GIN of layer 0)
    gemm_mma_kernel<1, true><<<dim3(DD / 64, NN / 32), 256>>>(
        x, in_w, in_b, h, NN, DD, DIN, pre, gin_eps);

    for (int l = 0; l < 2; l++) {
        // ---- GIN: pre already holds (1+eps_l)*h; add neighbor sums ----
        gin_agg_kernel<<<(EE * 64) / 256, 256>>>(ei, h, pre);
        gemm_mma_kernel<1, false><<<dim3(DD / 64, NN / 32), 256>>>(
            pre, mlp_w1 + (size_t)l * DD * DD, mlp_b1 + (size_t)l * DD, t, NN, DD, DD,
            nullptr, nullptr);
        gemm_mma_kernel<0, false><<<dim3(DD / 64, NN / 32), 256>>>(
            t, mlp_w2 + (size_t)l * DD * DD, mlp_b2 + (size_t)l * DD, t2, NN, DD, DD,
            nullptr, nullptr);
        ln_res_kernel<1, false><<<NN, 256>>>(
            t2, ln1_g + (size_t)l * DD, ln1_b + (size_t)l * DD, h, nullptr, nullptr);

        // ---- global attention ----
        gemm_mma_kernel<0, false><<<dim3(768 / 64, NN / 32), 256>>>(
            h, attn_in_w + (size_t)l * 768 * DD, attn_in_b + (size_t)l * 768, t, NN, 768, DD,
            nullptr, nullptr);
        flash_mma_kernel<<<dim3(NN / 128, HH), 256, FLASH_SMEM>>>(t, ao);
        gemm_mma_kernel<0, false><<<dim3(DD / 64, NN / 32), 256>>>(
            ao, attn_out_w + (size_t)l * DD * DD, attn_out_b + (size_t)l * DD, t2, NN, DD, DD,
            nullptr, nullptr);
        ln_res_kernel<0, false><<<NN, 256>>>(
            t2, ln2_g + (size_t)l * DD, ln2_b + (size_t)l * DD, h, nullptr, nullptr);

        // ---- FFN ----
        gemm_mma_kernel<2, false><<<dim3(512 / 64, NN / 32), 256>>>(
            h, ffn_w1 + (size_t)l * 512 * DD, ffn_b1 + (size_t)l * 512, t, NN, 512, DD,
            nullptr, nullptr);
        gemm_mma_kernel<0, false><<<dim3(DD / 64, NN / 32), 256>>>(
            t, ffn_w2 + (size_t)l * DD * 512, ffn_b2 + (size_t)l * DD, t2, NN, DD, 512,
            nullptr, nullptr);
        if (l == 0) {
            ln_res_kernel<0, true><<<NN, 256>>>(
                t2, ln3_g, ln3_b, h, pre, gin_eps + 1);
        } else {
            ln_res_kernel<0, false><<<NN, 256>>>(
                t2, ln3_g + (size_t)l * DD, ln3_b + (size_t)l * DD, h, nullptr, nullptr);
        }
    }

    // ---- head ----
    gemm_mma_kernel<1, false><<<dim3(DEMB / 64, NN / 32), 256>>>(
        h, head_w1, head_b1, emb, NN, DEMB, DD, nullptr, nullptr);
    head2_kernel<<<NN * 8 / 256, 256>>>(emb, head_w2, head_b2, (float*)d_out);
}

// round 17
// speedup vs baseline: 1.0650x; 1.0339x over previous
#include <cuda_runtime.h>
#include <cuda_bf16.h>
#include <math.h>

#define NN 4096
#define EE 131072
#define DIN 72
#define DD 256
#define HH 8
#define HDD 32
#define DEMB 128
#define TT 5

// ---------------- scratch (device globals; no runtime allocation) ----------------
__device__ float g_h  [NN * DD];
__device__ float g_pre[NN * DD];
__device__ float g_t  [NN * 768];
__device__ float g_ao [NN * DD];
__device__ float g_emb[NN * DEMB];

// ---------------- tf32 mma helpers ----------------
__device__ __forceinline__ unsigned cvt_tf32(float x) {
    unsigned r;
    asm("cvt.rna.tf32.f32 %0, %1;" : "=r"(r) : "f"(x));
    return r;
}
__device__ __forceinline__ void mma_tf32(float* c, const unsigned* a,
                                         unsigned b0, unsigned b1) {
    asm volatile(
        "mma.sync.aligned.m16n8k8.row.col.f32.tf32.tf32.f32 "
        "{%0,%1,%2,%3}, {%4,%5,%6,%7}, {%8,%9}, {%0,%1,%2,%3};\n"
        : "+f"(c[0]), "+f"(c[1]), "+f"(c[2]), "+f"(c[3])
        : "r"(a[0]), "r"(a[1]), "r"(a[2]), "r"(a[3]), "r"(b0), "r"(b1));
}

// ---------------- activations ----------------
__device__ __forceinline__ float act_elu(float v) {
    return v > 0.f ? v : expm1f(v);
}
__device__ __forceinline__ float act_gelu_tanh(float v) {
    const float c = 0.7978845608028654f;   // sqrt(2/pi)
    float u = c * (v + 0.044715f * v * v * v);
    return 0.5f * v * (1.f + tanhf(u));
}

// ---------------- tf32 MMA GEMM: C = act(A @ W^T + b) ----------------
// Block: 256 threads = 8 warps (2m x 4n), tile 32x64, BK=32 (zero-filled tail).
// WPRE: additionally write pre[m*256+n] = (1+eps[0])*C_val  (requires Nout==256).
template <int ACT, bool WPRE>
__global__ __launch_bounds__(256)
void gemm_mma_kernel(const float* __restrict__ A, const float* __restrict__ W,
                     const float* __restrict__ bias, float* __restrict__ C,
                     int M, int Nout, int K,
                     float* __restrict__ pre, const float* __restrict__ eps)
{
    __shared__ __align__(16) unsigned As[2][32][36];
    __shared__ __align__(16) unsigned Bs[2][64][36];

    const int tid = threadIdx.x;
    const int lane = tid & 31;
    const int wid = tid >> 5;
    const int gr = lane >> 2;
    const int gq = lane & 3;
    const int wm = (wid >> 2) * 16;
    const int wn = (wid & 3) * 16;
    const int m0 = blockIdx.y * 32, n0 = blockIdx.x * 64;

    float acc[2][4];
    #pragma unroll
    for (int ni = 0; ni < 2; ni++)
        #pragma unroll
        for (int f = 0; f < 4; f++) acc[ni][f] = 0.f;

    const int KT = (K + 31) >> 5;

    uint4 pa, pb[2];

    auto fetch = [&](int kt) {
        {
            int r = tid >> 3, cg = tid & 7;
            int k = kt * 32 + cg * 4;
            uint4 va = {0u, 0u, 0u, 0u};
            if (k < K) {
                float4 fa = *(const float4*)&A[(size_t)(m0 + r) * K + k];
                va.x = cvt_tf32(fa.x); va.y = cvt_tf32(fa.y);
                va.z = cvt_tf32(fa.z); va.w = cvt_tf32(fa.w);
            }
            pa = va;
        }
        #pragma unroll
        for (int u = 0; u < 2; u++) {
            int i = tid + u * 256;
            int r = i >> 3, cg = i & 7;
            int k = kt * 32 + cg * 4;
            uint4 vb = {0u, 0u, 0u, 0u};
            if (k < K) {
                float4 fb = *(const float4*)&W[(size_t)(n0 + r) * K + k];
                vb.x = cvt_tf32(fb.x); vb.y = cvt_tf32(fb.y);
                vb.z = cvt_tf32(fb.z); vb.w = cvt_tf32(fb.w);
            }
            pb[u] = vb;
        }
    };
    auto stash = [&](int buf) {
        {
            int r = tid >> 3, cg = tid & 7;
            *(uint4*)&As[buf][r][cg * 4] = pa;
        }
        #pragma unroll
        for (int u = 0; u < 2; u++) {
            int i = tid + u * 256;
            int r = i >> 3, cg = i & 7;
            *(uint4*)&Bs[buf][r][cg * 4] = pb[u];
        }
    };

    fetch(0);
    stash(0);
    __syncthreads();

    for (int kt = 0; kt < KT; kt++) {
        const int cur = kt & 1;
        if (kt + 1 < KT) fetch(kt + 1);

        const unsigned (*Ac)[36] = As[cur];
        const unsigned (*Bc)[36] = Bs[cur];
        #pragma unroll
        for (int kk = 0; kk < 4; kk++) {
            unsigned a[4];
            const int rr = wm + gr;
            a[0] = Ac[rr][kk * 8 + gq];
            a[1] = Ac[rr + 8][kk * 8 + gq];
            a[2] = Ac[rr][kk * 8 + gq + 4];
            a[3] = Ac[rr + 8][kk * 8 + gq + 4];
            #pragma unroll
            for (int ni = 0; ni < 2; ni++) {
                unsigned b0 = Bc[wn + ni * 8 + gr][kk * 8 + gq];
                unsigned b1 = Bc[wn + ni * 8 + gr][kk * 8 + gq + 4];
                mma_tf32(acc[ni], a, b0, b1);
            }
        }

        if (kt + 1 < KT) stash(cur ^ 1);
        __syncthreads();
    }

    float s = 1.f;
    if (WPRE) s = 1.f + eps[0];

    const int m = m0 + wm + gr;
    #pragma unroll
    for (int ni = 0; ni < 2; ni++) {
        const int n = n0 + wn + ni * 8 + 2 * gq;
        float b0 = bias[n], b1 = bias[n + 1];
        float2 w0, w1;
        w0.x = acc[ni][0] + b0; w0.y = acc[ni][1] + b1;
        w1.x = acc[ni][2] + b0; w1.y = acc[ni][3] + b1;
        if (ACT == 1) {
            w0.x = act_elu(w0.x); w0.y = act_elu(w0.y);
            w1.x = act_elu(w1.x); w1.y = act_elu(w1.y);
        }
        if (ACT == 2) {
            w0.x = act_gelu_tanh(w0.x); w0.y = act_gelu_tanh(w0.y);
            w1.x = act_gelu_tanh(w1.x); w1.y = act_gelu_tanh(w1.y);
        }
        *(float2*)&C[(size_t)m * Nout + n] = w0;
        *(float2*)&C[(size_t)(m + 8) * Nout + n] = w1;
        if (WPRE) {
            float2 p0, p1;
            p0.x = s * w0.x; p0.y = s * w0.y;
            p1.x = s * w1.x; p1.y = s * w1.y;
            *(float2*)&pre[(size_t)m * 256 + n] = p0;
            *(float2*)&pre[(size_t)(m + 8) * 256 + n] = p1;
        }
    }
}

// ---------------- fused GEMM(Nout=256) + LayerNorm + residual ----------------
// Block: 1024 threads = 32 warps (2m x 16n), strip 32 x 256, BK=32.
// h += lnact(LN(A @ W^T + bias)); WPRE: pre = (1+eps[0]) * h_new.
// Dynamic smem: As[2][32][36] | Bs[2][256][36]; Cs[32][258] overlays Bs after loop.
template <int LACT, bool WPRE>
__global__ __launch_bounds__(1024)
void gemm_ln_kernel(const float* __restrict__ A, const float* __restrict__ W,
                    const float* __restrict__ bias,
                    const float* __restrict__ g, const float* __restrict__ b,
                    float* __restrict__ h, int K,
                    float* __restrict__ pre, const float* __restrict__ eps)
{
    extern __shared__ __align__(16) unsigned lsm[];
    unsigned (*As)[32][36]  = (unsigned(*)[32][36])lsm;
    unsigned (*Bs)[256][36] = (unsigned(*)[256][36])(lsm + 2 * 32 * 36);
    float (*Cs)[258]        = (float(*)[258])(lsm + 2 * 32 * 36);  // overlays Bs

    const int tid = threadIdx.x;
    const int lane = tid & 31;
    const int wid = tid >> 5;           // 0..31
    const int gr = lane >> 2;
    const int gq = lane & 3;
    const int wm = (wid >> 4) * 16;     // 0,16
    const int wn = (wid & 15) * 16;     // 0..240
    const int m0 = blockIdx.x * 32;

    float acc[2][4];
    #pragma unroll
    for (int ni = 0; ni < 2; ni++)
        #pragma unroll
        for (int f = 0; f < 4; f++) acc[ni][f] = 0.f;

    const int KT = K >> 5;

    uint4 pa, pb[2];

    auto fetch = [&](int kt) {
        if (tid < 256) {
            int r = tid >> 3, cg = tid & 7;
            int k = kt * 32 + cg * 4;
            float4 fa = *(const float4*)&A[(size_t)(m0 + r) * K + k];
            pa.x = cvt_tf32(fa.x); pa.y = cvt_tf32(fa.y);
            pa.z = cvt_tf32(fa.z); pa.w = cvt_tf32(fa.w);
        }
        #pragma unroll
        for (int u = 0; u < 2; u++) {
            int i = tid + u * 1024;
            int r = i >> 3, cg = i & 7;
            int k = kt * 32 + cg * 4;
            float4 fb = *(const float4*)&W[(size_t)r * K + k];
            pb[u].x = cvt_tf32(fb.x); pb[u].y = cvt_tf32(fb.y);
            pb[u].z = cvt_tf32(fb.z); pb[u].w = cvt_tf32(fb.w);
        }
    };
    auto stash = [&](int buf) {
        if (tid < 256) {
            int r = tid >> 3, cg = tid & 7;
            *(uint4*)&As[buf][r][cg * 4] = pa;
        }
        #pragma unroll
        for (int u = 0; u < 2; u++) {
            int i = tid + u * 1024;
            int r = i >> 3, cg = i & 7;
            *(uint4*)&Bs[buf][r][cg * 4] = pb[u];
        }
    };

    fetch(0);
    stash(0);
    __syncthreads();

    for (int kt = 0; kt < KT; kt++) {
        const int cur = kt & 1;
        if (kt + 1 < KT) fetch(kt + 1);

        const unsigned (*Ac)[36] = As[cur];
        const unsigned (*Bc)[36] = Bs[cur];
        #pragma unroll
        for (int kk = 0; kk < 4; kk++) {
            unsigned a[4];
            const int rr = wm + gr;
            a[0] = Ac[rr][kk * 8 + gq];
            a[1] = Ac[rr + 8][kk * 8 + gq];
            a[2] = Ac[rr][kk * 8 + gq + 4];
            a[3] = Ac[rr + 8][kk * 8 + gq + 4];
            #pragma unroll
            for (int ni = 0; ni < 2; ni++) {
                unsigned b0 = Bc[wn + ni * 8 + gr][kk * 8 + gq];
                unsigned b1 = Bc[wn + ni * 8 + gr][kk * 8 + gq + 4];
                mma_tf32(acc[ni], a, b0, b1);
            }
        }

        if (kt + 1 < KT) stash(cur ^ 1);
        __syncthreads();
    }
    // after the final __syncthreads all Bs reads are done; Cs may overlay it

    {
        const int m = wm + gr;      // local row
        #pragma unroll
        for (int ni = 0; ni < 2; ni++) {
            const int n = wn + ni * 8 + 2 * gq;
            float b0 = bias[n], b1 = bias[n + 1];
            float2 w0, w1;
            w0.x = acc[ni][0] + b0; w0.y = acc[ni][1] + b1;
            w1.x = acc[ni][2] + b0; w1.y = acc[ni][3] + b1;
            *(float2*)&Cs[m][n] = w0;
            *(float2*)&Cs[m + 8][n] = w1;
        }
    }
    __syncthreads();

    // LN: one warp per row
    {
        const int row = wid;                 // 0..31
        const int gm = m0 + row;
        float v[8];
        float s1 = 0.f, s2 = 0.f;
        #pragma unroll
        for (int j = 0; j < 8; j++) {
            float x = Cs[row][lane + 32 * j];
            v[j] = x;
            s1 += x;
            s2 += x * x;
        }
        #pragma unroll
        for (int off = 16; off > 0; off >>= 1) {
            s1 += __shfl_xor_sync(0xffffffffu, s1, off);
            s2 += __shfl_xor_sync(0xffffffffu, s2, off);
        }
        float mu = s1 * (1.f / DD);
        float var = s2 * (1.f / DD) - mu * mu;
        float rinv = rsqrtf(var + 1e-5f);
        float sw = 1.f;
        if (WPRE) sw = 1.f + eps[0];
        #pragma unroll
        for (int j = 0; j < 8; j++) {
            int col = lane + 32 * j;
            float y = (v[j] - mu) * rinv * g[col] + b[col];
            if (LACT == 1) y = act_elu(y);
            float xn = h[(size_t)gm * DD + col] + y;
            h[(size_t)gm * DD + col] = xn;
            if (WPRE) pre[(size_t)gm * DD + col] = sw * xn;
        }
    }
}

#define GEMMLN_SMEM ((2 * 32 * 36 + 2 * 256 * 36) * 4)   // 82944 B

// ---------------- dedicated head-2 kernel: out[4096,5] = emb @ w2^T + b2 ----------------
__global__ __launch_bounds__(256)
void head2_kernel(const float* __restrict__ emb, const float* __restrict__ w,
                  const float* __restrict__ b, float* __restrict__ out)
{
    int idx = blockIdx.x * 256 + threadIdx.x;
    int row = idx >> 3, col = idx & 7;
    if (col >= TT) return;
    const float4* er = (const float4*)&emb[(size_t)row * DEMB];
    const float4* wr = (const float4*)&w[(size_t)col * DEMB];
    float s = 0.f;
    #pragma unroll
    for (int k = 0; k < DEMB / 4; k++) {
        float4 a = er[k];
        float4 c = wr[k];
        s += a.x * c.x + a.y * c.y + a.z * c.z + a.w * c.w;
    }
    out[(size_t)row * TT + col] = s + b[col];
}

// ---------------- GIN edge aggregation: vector red.global.add.v4.f32 ----------------
__global__ __launch_bounds__(256)
void gin_agg_kernel(const int* __restrict__ ei,
                    const float* __restrict__ x, float* __restrict__ pre)
{
    long long gid = (long long)blockIdx.x * blockDim.x + threadIdx.x;
    int e = (int)(gid >> 6);
    int c = ((int)gid & 63) * 4;
    if (e >= EE) return;
    int src = ei[e];
    int dst = ei[EE + e];
    float4 v = *(const float4*)&x[src * DD + c];
    float* a = &pre[dst * DD + c];
    asm volatile("red.global.add.v4.f32 [%0], {%1, %2, %3, %4};"
                 :: "l"(a), "f"(v.x), "f"(v.y), "f"(v.z), "f"(v.w)
                 : "memory");
}

// ---------------- flash attention via tf32 mma.sync, BM=128, KV tile 128 ----------------
__global__ __launch_bounds__(256)
void flash_mma_kernel(const float* __restrict__ qkv, float* __restrict__ out)
{
    extern __shared__ __align__(16) unsigned fsm[];
    unsigned (*Ks)[36]  = (unsigned(*)[36])fsm;
    unsigned (*Vs)[36]  = (unsigned(*)[36])(fsm + 128 * 36);
    unsigned (*Ps)[132] = (unsigned(*)[132])(fsm + 2 * 128 * 36);

    const int tid = threadIdx.x;
    const int lane = tid & 31;
    const int wid = tid >> 5;
    const int hh = blockIdx.y;
    const int q0 = blockIdx.x * 128;
    const int gr = lane >> 2;
    const int gq = lane & 3;
    const float scale = 0.17677669529663689f;  // 1/sqrt(32)

    const int r0 = wid * 16 + gr;
    const int r1 = r0 + 8;

    unsigned aq[4][4];
    {
        const float* p0 = &qkv[(q0 + r0) * 768 + hh * 32];
        const float* p1 = &qkv[(q0 + r1) * 768 + hh * 32];
        #pragma unroll
        for (int kk = 0; kk < 4; kk++) {
            aq[kk][0] = cvt_tf32(p0[kk * 8 + gq] * scale);
            aq[kk][1] = cvt_tf32(p1[kk * 8 + gq] * scale);
            aq[kk][2] = cvt_tf32(p0[kk * 8 + gq + 4] * scale);
            aq[kk][3] = cvt_tf32(p1[kk * 8 + gq + 4] * scale);
        }
    }

    float m0 = -1e30f, l0 = 0.f, m1 = -1e30f, l1 = 0.f;
    float o[4][4];
    #pragma unroll
    for (int n = 0; n < 4; n++)
        #pragma unroll
        for (int f = 0; f < 4; f++) o[n][f] = 0.f;

    for (int t0 = 0; t0 < NN; t0 += 128) {
        __syncthreads();
        #pragma unroll
        for (int i = tid; i < 1024; i += 256) {
            int r = i >> 3, d = (i & 7) * 4;
            float4 kv = *(const float4*)&qkv[(t0 + r) * 768 + 256 + hh * 32 + d];
            float4 vv = *(const float4*)&qkv[(t0 + r) * 768 + 512 + hh * 32 + d];
            uint4 kt, vt;
            kt.x = cvt_tf32(kv.x); kt.y = cvt_tf32(kv.y);
            kt.z = cvt_tf32(kv.z); kt.w = cvt_tf32(kv.w);
            vt.x = cvt_tf32(vv.x); vt.y = cvt_tf32(vv.y);
            vt.z = cvt_tf32(vv.z); vt.w = cvt_tf32(vv.w);
            *(uint4*)&Ks[r][d] = kt;
            *(uint4*)&Vs[r][d] = vt;
        }
        __syncthreads();

        float sc[16][4];
        #pragma unroll
        for (int nn = 0; nn < 16; nn++) {
            sc[nn][0] = 0.f; sc[nn][1] = 0.f; sc[nn][2] = 0.f; sc[nn][3] = 0.f;
            #pragma unroll
            for (int kk = 0; kk < 4; kk++) {
                unsigned b0 = Ks[nn * 8 + gr][kk * 8 + gq];
                unsigned b1 = Ks[nn * 8 + gr][kk * 8 + gq + 4];
                mma_tf32(sc[nn], aq[kk], b0, b1);
            }
        }

        float rmax0 = -1e30f, rmax1 = -1e30f;
        #pragma unroll
        for (int nn = 0; nn < 16; nn++) {
            rmax0 = fmaxf(rmax0, fmaxf(sc[nn][0], sc[nn][1]));
            rmax1 = fmaxf(rmax1, fmaxf(sc[nn][2], sc[nn][3]));
        }
        rmax0 = fmaxf(rmax0, __shfl_xor_sync(0xffffffffu, rmax0, 1));
        rmax0 = fmaxf(rmax0, __shfl_xor_sync(0xffffffffu, rmax0, 2));
        rmax1 = fmaxf(rmax1, __shfl_xor_sync(0xffffffffu, rmax1, 1));
        rmax1 = fmaxf(rmax1, __shfl_xor_sync(0xffffffffu, rmax1, 2));

        float nm0 = fmaxf(m0, rmax0), alpha0 = __expf(m0 - nm0);
        float nm1 = fmaxf(m1, rmax1), alpha1 = __expf(m1 - nm1);

        float ps0 = 0.f, ps1 = 0.f;
        #pragma unroll
        for (int nn = 0; nn < 16; nn++) {
            float p00 = __expf(sc[nn][0] - nm0);
            float p01 = __expf(sc[nn][1] - nm0);
            float p10 = __expf(sc[nn][2] - nm1);
            float p11 = __expf(sc[nn][3] - nm1);
            ps0 += p00 + p01;
            ps1 += p10 + p11;
            uint2 w0, w1;
            w0.x = cvt_tf32(p00); w0.y = cvt_tf32(p01);
            w1.x = cvt_tf32(p10); w1.y = cvt_tf32(p11);
            *(uint2*)&Ps[r0][nn * 8 + 2 * gq] = w0;
            *(uint2*)&Ps[r1][nn * 8 + 2 * gq] = w1;
        }
        ps0 += __shfl_xor_sync(0xffffffffu, ps0, 1);
        ps0 += __shfl_xor_sync(0xffffffffu, ps0, 2);
        ps1 += __shfl_xor_sync(0xffffffffu, ps1, 1);
        ps1 += __shfl_xor_sync(0xffffffffu, ps1, 2);

        l0 = l0 * alpha0 + ps0; m0 = nm0;
        l1 = l1 * alpha1 + ps1; m1 = nm1;

        #pragma unroll
        for (int nn = 0; nn < 4; nn++) {
            o[nn][0] *= alpha0; o[nn][1] *= alpha0;
            o[nn][2] *= alpha1; o[nn][3] *= alpha1;
        }

        __syncwarp();

        #pragma unroll
        for (int kk = 0; kk < 16; kk++) {
            unsigned pa[4];
            pa[0] = Ps[r0][kk * 8 + gq];
            pa[1] = Ps[r1][kk * 8 + gq];
            pa[2] = Ps[r0][kk * 8 + gq + 4];
            pa[3] = Ps[r1][kk * 8 + gq + 4];
            #pragma unroll
            for (int nn = 0; nn < 4; nn++) {
                unsigned b0 = Vs[kk * 8 + gq][nn * 8 + gr];
                unsigned b1 = Vs[kk * 8 + gq + 4][nn * 8 + gr];
                mma_tf32(o[nn], pa, b0, b1);
            }
        }
        __syncwarp();
    }

    const float inv0 = 1.f / l0, inv1 = 1.f / l1;
    #pragma unroll
    for (int nn = 0; nn < 4; nn++) {
        float2 w0, w1;
        w0.x = o[nn][0] * inv0; w0.y = o[nn][1] * inv0;
        w1.x = o[nn][2] * inv1; w1.y = o[nn][3] * inv1;
        *(float2*)&out[(q0 + r0) * DD + hh * 32 + nn * 8 + 2 * gq] = w0;
        *(float2*)&out[(q0 + r1) * DD + hh * 32 + nn * 8 + 2 * gq] = w1;
    }
}

// ---------------- host orchestration ----------------
extern "C" void kernel_launch(void* const* d_in, const int* in_sizes, int n_in,
                              void* d_out, int out_size)
{
    const float*     x         = (const float*)d_in[0];
    const int*       ei        = (const int*)d_in[1];
    const float*     in_w      = (const float*)d_in[2];
    const float*     in_b      = (const float*)d_in[3];
    const float*     head_w1   = (const float*)d_in[4];
    const float*     head_b1   = (const float*)d_in[5];
    const float*     head_w2   = (const float*)d_in[6];
    const float*     head_b2   = (const float*)d_in[7];
    const float*     mlp_w1    = (const float*)d_in[8];
    const float*     mlp_b1    = (const float*)d_in[9];
    const float*     mlp_w2    = (const float*)d_in[10];
    const float*     mlp_b2    = (const float*)d_in[11];
    const float*     gin_eps   = (const float*)d_in[12];
    const float*     ln1_g     = (const float*)d_in[13];
    const float*     ln1_b     = (const float*)d_in[14];
    const float*     attn_in_w = (const float*)d_in[15];
    const float*     attn_in_b = (const float*)d_in[16];
    const float*     attn_out_w= (const float*)d_in[17];
    const float*     attn_out_b= (const float*)d_in[18];
    const float*     ln2_g     = (const float*)d_in[19];
    const float*     ln2_b     = (const float*)d_in[20];
    const float*     ffn_w1    = (const float*)d_in[21];
    const float*     ffn_b1    = (const float*)d_in[22];
    const float*     ffn_w2    = (const float*)d_in[23];
    const float*     ffn_b2    = (const float*)d_in[24];
    const float*     ln3_g     = (const float*)d_in[25];
    const float*     ln3_b     = (const float*)d_in[26];

    float *h, *pre, *t, *ao, *emb;
    cudaGetSymbolAddress((void**)&h,   g_h);
    cudaGetSymbolAddress((void**)&pre, g_pre);
    cudaGetSymbolAddress((void**)&t,   g_t);
    cudaGetSymbolAddress((void**)&ao,  g_ao);
    cudaGetSymbolAddress((void**)&emb, g_emb);

    const int FLASH_SMEM = (2 * 128 * 36 + 128 * 132) * 4;   // 104448 B
    cudaFuncSetAttribute(flash_mma_kernel,
                         cudaFuncAttributeMaxDynamicSharedMemorySize, FLASH_SMEM);
    cudaFuncSetAttribute(gemm_ln_kernel<1, false>,
                         cudaFuncAttributeMaxDynamicSharedMemorySize, GEMMLN_SMEM);
    cudaFuncSetAttribute(gemm_ln_kernel<0, false>,
                         cudaFuncAttributeMaxDynamicSharedMemorySize, GEMMLN_SMEM);
    cudaFuncSetAttribute(gemm_ln_kernel<0, true>,
                         cudaFuncAttributeMaxDynamicSharedMemorySize, GEMMLN_SMEM);

    // input proj + ELU; also writes pre = (1+eps[0]) * h  (GIN of layer 0)
    gemm_mma_kernel<1, true><<<dim3(DD / 64, NN / 32), 256>>>(
        x, in_w, in_b, h, NN, DD, DIN, pre, gin_eps);

    for (int l = 0; l < 2; l++) {
        // ---- GIN: pre already holds (1+eps_l)*h; add neighbor sums ----
        gin_agg_kernel<<<(EE * 64) / 256, 256>>>(ei, h, pre);
        gemm_mma_kernel<1, false><<<dim3(DD / 64, NN / 32), 256>>>(
            pre, mlp_w1 + (size_t)l * DD * DD, mlp_b1 + (size_t)l * DD, t, NN, DD, DD,
            nullptr, nullptr);
        // mlp2 + LN1(+ELU) + residual, fused
        gemm_ln_kernel<1, false><<<NN / 32, 1024, GEMMLN_SMEM>>>(
            t, mlp_w2 + (size_t)l * DD * DD, mlp_b2 + (size_t)l * DD,
            ln1_g + (size_t)l * DD, ln1_b + (size_t)l * DD, h, DD,
            nullptr, nullptr);

        // ---- global attention ----
        gemm_mma_kernel<0, false><<<dim3(768 / 64, NN / 32), 256>>>(
            h, attn_in_w + (size_t)l * 768 * DD, attn_in_b + (size_t)l * 768, t, NN, 768, DD,
            nullptr, nullptr);
        flash_mma_kernel<<<dim3(NN / 128, HH), 256, FLASH_SMEM>>>(t, ao);
        // attn_out + LN2 + residual, fused
        gemm_ln_kernel<0, false><<<NN / 32, 1024, GEMMLN_SMEM>>>(
            ao, attn_out_w + (size_t)l * DD * DD, attn_out_b + (size_t)l * DD,
            ln2_g + (size_t)l * DD, ln2_b + (size_t)l * DD, h, DD,
            nullptr, nullptr);

        // ---- FFN ----
        gemm_mma_kernel<2, false><<<dim3(512 / 64, NN / 32), 256>>>(
            h, ffn_w1 + (size_t)l * 512 * DD, ffn_b1 + (size_t)l * 512, t, NN, 512, DD,
            nullptr, nullptr);
        // ffn2 + LN3 + residual, fused (layer 0 also seeds pre for layer 1)
        if (l == 0) {
            gemm_ln_kernel<0, true><<<NN / 32, 1024, GEMMLN_SMEM>>>(
                t, ffn_w2, ffn_b2, ln3_g, ln3_b, h, 512, pre, gin_eps + 1);
        } else {
            gemm_ln_kernel<0, false><<<NN / 32, 1024, GEMMLN_SMEM>>>(
                t, ffn_w2 + (size_t)l * DD * 512, ffn_b2 + (size_t)l * DD,
                ln3_g + (size_t)l * DD, ln3_b + (size_t)l * DD, h, 512,
                nullptr, nullptr);
        }
    }

    // ---- head ----
    gemm_mma_kernel<1, false><<<dim3(DEMB / 64, NN / 32), 256>>>(
        h, head_w1, head_b1, emb, NN, DEMB, DD, nullptr, nullptr);
    head2_kernel<<<NN * 8 / 256, 256>>>(emb, head_w2, head_b2, (float*)d_out);
}